// round 2
// baseline (speedup 1.0000x reference)
#include <cuda_runtime.h>
#include <cuda_bf16.h>
#include <cstdint>

#define B_      16
#define N_SP    2048
#define N_TM    64
#define M_OUT   2112
#define M_PAD   2176
#define KD      64
#define TILE    128
#define NTILES  17

// Scratch: bf16 hi/lo splits of concatenated+padded node embeddings.
// 16 * 2176 * 64 * 2B = 4.45 MB each (L2-resident working set).
__device__ __nv_bfloat16 g_hi[B_ * M_PAD * KD];
__device__ __nv_bfloat16 g_lo[B_ * M_PAD * KD];

// ---------------------------------------------------------------------------
// Pass 1: fp32 -> bf16 hi/lo split, concat(spatial, temporal), zero-pad rows.
// ---------------------------------------------------------------------------
__global__ void convert_split_kernel(const float4* __restrict__ sp,
                                     const float4* __restrict__ tp) {
    const int TOT = B_ * M_PAD * (KD / 4);
    int idx = blockIdx.x * blockDim.x + threadIdx.x;
    if (idx >= TOT) return;
    int kq  = idx & 15;              // float4 index within a 64-elem row
    int row = (idx >> 4) % M_PAD;
    int b   = idx / (M_PAD * 16);

    float4 x = make_float4(0.f, 0.f, 0.f, 0.f);
    if (row < N_SP)
        x = sp[((long)b * N_SP + row) * 16 + kq];
    else if (row < M_OUT)
        x = tp[((long)b * N_TM + (row - N_SP)) * 16 + kq];

    float xf[4] = {x.x, x.y, x.z, x.w};
    union { __nv_bfloat16 h[4]; uint2 u; } uh;
    union { __nv_bfloat16 h[4]; uint2 u; } ul;
#pragma unroll
    for (int i = 0; i < 4; i++) {
        __nv_bfloat16 h = __float2bfloat16(xf[i]);
        float lo = xf[i] - __bfloat162float(h);
        uh.h[i] = h;
        ul.h[i] = __float2bfloat16(lo);
    }
    *reinterpret_cast<uint2*>(&g_hi[(long)idx * 4]) = uh.u;
    *reinterpret_cast<uint2*>(&g_lo[(long)idx * 4]) = ul.u;
}

// ---------------------------------------------------------------------------
// PTX helpers (portable compute_103: mma.sync + ldmatrix + tanh.approx)
// ---------------------------------------------------------------------------
__device__ __forceinline__ uint32_t smem_u32(const void* p) {
    uint32_t a;
    asm("{ .reg .u64 t; cvta.to.shared.u64 t, %1; cvt.u32.u64 %0, t; }"
        : "=r"(a) : "l"(p));
    return a;
}

__device__ __forceinline__ void ldsm_x4(uint32_t* r, uint32_t addr) {
    asm volatile("ldmatrix.sync.aligned.m8n8.x4.shared.b16 {%0,%1,%2,%3}, [%4];"
                 : "=r"(r[0]), "=r"(r[1]), "=r"(r[2]), "=r"(r[3]) : "r"(addr));
}

__device__ __forceinline__ void mma16816(float* c, const uint32_t* a,
                                         uint32_t b0, uint32_t b1) {
    asm volatile(
        "mma.sync.aligned.m16n8k16.row.col.f32.bf16.bf16.f32 "
        "{%0,%1,%2,%3}, {%4,%5,%6,%7}, {%8,%9}, {%0,%1,%2,%3};"
        : "+f"(c[0]), "+f"(c[1]), "+f"(c[2]), "+f"(c[3])
        : "r"(a[0]), "r"(a[1]), "r"(a[2]), "r"(a[3]), "r"(b0), "r"(b1));
}

// tanh(relu(x)) via HW MUFU.TANH (1 MUFU/elem; abs err <~5e-4 only in the
// small transition band, exact at 0 and in saturation).
__device__ __forceinline__ float tanh_relu(float x) {
    x = fmaxf(x, 0.0f);
    float y;
    asm("tanh.approx.f32 %0, %1;" : "=f"(y) : "f"(x));
    return y;
}

// ---------------------------------------------------------------------------
// Pass 2: one CTA (256 thr, 8 warps) per 128x128 output tile.
// SMEM rows padded to 144B for conflict-free ldmatrix.
// ---------------------------------------------------------------------------
#define ROWB       144
#define TILE_B     (128 * ROWB)          // 18432 B per operand tile
#define SMEM_BYTES (4 * TILE_B)          // A_hi, A_lo, B_hi, B_lo = 73728 B

__global__ void __launch_bounds__(256, 2)
gram_kernel(float* __restrict__ out) {
    extern __shared__ char smem[];
    const int tid = threadIdx.x;
    const int lid = tid & 31;
    const int wid = tid >> 5;
    const int wr  = wid >> 2;            // warp row 0..1  (64 rows each)
    const int wc  = wid & 3;             // warp col 0..3  (32 cols each)
    const int ti = blockIdx.x, tj = blockIdx.y, b = blockIdx.z;

    // --- Stage 4 operand tiles (128 rows x 128B payload, 144B pitch) -------
    {
        const uint4* hi4 = reinterpret_cast<const uint4*>(g_hi);
        const uint4* lo4 = reinterpret_cast<const uint4*>(g_lo);
        const long baseA = ((long)b * M_PAD + (long)ti * TILE) * 8;  // uint4/row
        const long baseB = ((long)b * M_PAD + (long)tj * TILE) * 8;
#pragma unroll
        for (int it = 0; it < 4; it++) {
            int idx = it * 256 + tid;        // 0..1023
            int row = idx >> 3, seg = idx & 7;
            int so = row * ROWB + seg * 16;
            long offA = baseA + row * 8 + seg;
            long offB = baseB + row * 8 + seg;
            *reinterpret_cast<uint4*>(smem + 0 * TILE_B + so) = hi4[offA];
            *reinterpret_cast<uint4*>(smem + 1 * TILE_B + so) = lo4[offA];
            *reinterpret_cast<uint4*>(smem + 2 * TILE_B + so) = hi4[offB];
            *reinterpret_cast<uint4*>(smem + 3 * TILE_B + so) = lo4[offB];
        }
    }
    __syncthreads();

    const uint32_t sb = smem_u32(smem);
    // ldmatrix lane address offsets (lane 0..15 -> rows, lane>>4 -> k-half)
    const uint32_t a_lane = (uint32_t)(wr * 64 + (lid & 15)) * ROWB + (lid >> 4) * 16;
    const uint32_t b_lane = (uint32_t)(wc * 32 + (lid & 15)) * ROWB + (lid >> 4) * 16;

    float acc[4][4][4];
#pragma unroll
    for (int mt = 0; mt < 4; mt++)
#pragma unroll
        for (int nt = 0; nt < 4; nt++)
#pragma unroll
            for (int q = 0; q < 4; q++) acc[mt][nt][q] = 0.0f;

    // splits: hi*hi + hi*lo + lo*hi   (A tile offset, B tile offset)
    const uint32_t splitA[3] = {0 * TILE_B, 0 * TILE_B, 1 * TILE_B};
    const uint32_t splitB[3] = {2 * TILE_B, 3 * TILE_B, 2 * TILE_B};

#pragma unroll
    for (int s = 0; s < 3; s++) {
        const uint32_t abase = sb + splitA[s] + a_lane;
        const uint32_t bbase = sb + splitB[s] + b_lane;
#pragma unroll
        for (int k = 0; k < 4; k++) {            // K = 4 x 16
            uint32_t af[4][4], bf[2][4];
#pragma unroll
            for (int mt = 0; mt < 4; mt++)
                ldsm_x4(af[mt], abase + mt * 16 * ROWB + k * 32);
#pragma unroll
            for (int bt = 0; bt < 2; bt++)
                ldsm_x4(bf[bt], bbase + bt * 16 * ROWB + k * 32);
#pragma unroll
            for (int mt = 0; mt < 4; mt++)
#pragma unroll
                for (int nt = 0; nt < 4; nt++)
                    mma16816(acc[mt][nt], af[mt],
                             bf[nt >> 1][nt & 1], bf[nt >> 1][(nt & 1) + 2]);
        }
    }

    // --- Epilogue: tanh(relu(.)) + 0.5*I, direct fragment stores -----------
    // c0,c1 -> (r0, c), (r0, c+1); c2,c3 -> (r0+8, ...)
    const int row0 = ti * TILE + wr * 64 + (lid >> 2);
    const int col0 = tj * TILE + wc * 32 + (lid & 3) * 2;
#pragma unroll
    for (int mt = 0; mt < 4; mt++) {
#pragma unroll
        for (int nt = 0; nt < 4; nt++) {
            int c = col0 + nt * 8;
#pragma unroll
            for (int h = 0; h < 2; h++) {        // row halves r0, r0+8
                int r = row0 + mt * 16 + h * 8;
                float2 v;
                v.x = tanh_relu(acc[mt][nt][h * 2 + 0]);
                v.y = tanh_relu(acc[mt][nt][h * 2 + 1]);
                if (r == c)     v.x += 0.5f;
                if (r == c + 1) v.y += 0.5f;
                if (r < M_OUT && c < M_OUT)
                    *reinterpret_cast<float2*>(
                        out + ((long)b * M_OUT + r) * M_OUT + c) = v;
            }
        }
    }
}

// ---------------------------------------------------------------------------
extern "C" void kernel_launch(void* const* d_in, const int* in_sizes, int n_in,
                              void* d_out, int out_size) {
    const float* sp = (const float*)d_in[0];
    const float* tp = (const float*)d_in[1];
    if (n_in >= 2 && in_sizes[0] < in_sizes[1]) {   // defensive order check
        sp = (const float*)d_in[1];
        tp = (const float*)d_in[0];
    }
    float* out = (float*)d_out;

    const int TOT = B_ * M_PAD * (KD / 4);
    convert_split_kernel<<<(TOT + 255) / 256, 256>>>(
        (const float4*)sp, (const float4*)tp);

    cudaFuncSetAttribute(gram_kernel,
                         cudaFuncAttributeMaxDynamicSharedMemorySize, SMEM_BYTES);
    dim3 grid(NTILES, NTILES, B_);
    gram_kernel<<<grid, 256, SMEM_BYTES>>>(out);
}

// round 3
// speedup vs baseline: 1.7369x; 1.7369x over previous
#include <cuda_runtime.h>
#include <cuda_bf16.h>
#include <cstdint>

#define B_      16
#define N_SP    2048
#define N_TM    64
#define M_OUT   2112
#define M_PAD   2176
#define KD      64
#define TILE    128
#define NTILES  17
#define NPAIRS  153      // 17*18/2 upper-triangular tile pairs

// Scratch: bf16 hi/lo splits of concatenated+padded node embeddings.
__device__ __nv_bfloat16 g_hi[B_ * M_PAD * KD];
__device__ __nv_bfloat16 g_lo[B_ * M_PAD * KD];

// ---------------------------------------------------------------------------
// Pass 1: fp32 -> bf16 hi/lo split, concat(spatial, temporal), zero-pad rows.
// ---------------------------------------------------------------------------
__global__ void convert_split_kernel(const float4* __restrict__ sp,
                                     const float4* __restrict__ tp) {
    const int TOT = B_ * M_PAD * (KD / 4);
    int idx = blockIdx.x * blockDim.x + threadIdx.x;
    if (idx >= TOT) return;
    int kq  = idx & 15;
    int row = (idx >> 4) % M_PAD;
    int b   = idx / (M_PAD * 16);

    float4 x = make_float4(0.f, 0.f, 0.f, 0.f);
    if (row < N_SP)
        x = sp[((long)b * N_SP + row) * 16 + kq];
    else if (row < M_OUT)
        x = tp[((long)b * N_TM + (row - N_SP)) * 16 + kq];

    float xf[4] = {x.x, x.y, x.z, x.w};
    union { __nv_bfloat16 h[4]; uint2 u; } uh;
    union { __nv_bfloat16 h[4]; uint2 u; } ul;
#pragma unroll
    for (int i = 0; i < 4; i++) {
        __nv_bfloat16 h = __float2bfloat16(xf[i]);
        float lo = xf[i] - __bfloat162float(h);
        uh.h[i] = h;
        ul.h[i] = __float2bfloat16(lo);
    }
    *reinterpret_cast<uint2*>(&g_hi[(long)idx * 4]) = uh.u;
    *reinterpret_cast<uint2*>(&g_lo[(long)idx * 4]) = ul.u;
}

// ---------------------------------------------------------------------------
// PTX helpers (portable compute_103: mma.sync + ldmatrix + tanh.approx)
// ---------------------------------------------------------------------------
__device__ __forceinline__ uint32_t smem_u32(const void* p) {
    uint32_t a;
    asm("{ .reg .u64 t; cvta.to.shared.u64 t, %1; cvt.u32.u64 %0, t; }"
        : "=r"(a) : "l"(p));
    return a;
}

__device__ __forceinline__ void ldsm_x4(uint32_t* r, uint32_t addr) {
    asm volatile("ldmatrix.sync.aligned.m8n8.x4.shared.b16 {%0,%1,%2,%3}, [%4];"
                 : "=r"(r[0]), "=r"(r[1]), "=r"(r[2]), "=r"(r[3]) : "r"(addr));
}

__device__ __forceinline__ void mma16816(float* c, const uint32_t* a,
                                         uint32_t b0, uint32_t b1) {
    asm volatile(
        "mma.sync.aligned.m16n8k16.row.col.f32.bf16.bf16.f32 "
        "{%0,%1,%2,%3}, {%4,%5,%6,%7}, {%8,%9}, {%0,%1,%2,%3};"
        : "+f"(c[0]), "+f"(c[1]), "+f"(c[2]), "+f"(c[3])
        : "r"(a[0]), "r"(a[1]), "r"(a[2]), "r"(a[3]), "r"(b0), "r"(b1));
}

__device__ __forceinline__ float tanh_relu(float x) {
    x = fmaxf(x, 0.0f);
    float y;
    asm("tanh.approx.f32 %0, %1;" : "=f"(y) : "f"(x));
    return y;
}

// ---------------------------------------------------------------------------
// Pass 2: one CTA (256 thr, 8 warps) per upper-triangular 128x128 tile pair.
// Mainloop: bf16 3-split gram with A-fragment reuse. Epilogue: direct store
// + mirrored store via conflict-free SMEM transpose.
// ---------------------------------------------------------------------------
#define ROWB       144                   // smem operand pitch (bytes)
#define TILE_B     (128 * ROWB)          // 18432 B per operand tile
#define SMEM_BYTES (4 * TILE_B)          // 73728 B (also covers 128x132 f32)
#define TPITCH     132                   // transpose buffer pitch (floats)

__global__ void __launch_bounds__(256, 2)
gram_kernel(float* __restrict__ out) {
    extern __shared__ char smem[];
    const int tid = threadIdx.x;
    const int lid = tid & 31;
    const int wid = tid >> 5;
    const int wr  = wid >> 2;            // warp row 0..1  (64 rows)
    const int wc  = wid & 3;             // warp col 0..3  (32 cols)
    const int b   = blockIdx.y;

    // Decode upper-triangular pair index -> (ti, tj), ti <= tj.
    int ti = 0, rem = blockIdx.x;
    while (rem >= NTILES - ti) { rem -= NTILES - ti; ti++; }
    const int tj = ti + rem;
    const bool diag = (ti == tj);

    const uint32_t A_HI = 0, A_LO = TILE_B;
    const uint32_t B_HI = diag ? A_HI : 2u * TILE_B;
    const uint32_t B_LO = diag ? A_LO : 3u * TILE_B;

    // --- Stage operand tiles (128 rows x 128B payload, 144B pitch) ---------
    {
        const uint4* hi4 = reinterpret_cast<const uint4*>(g_hi);
        const uint4* lo4 = reinterpret_cast<const uint4*>(g_lo);
        const long baseA = ((long)b * M_PAD + (long)ti * TILE) * 8;
        const long baseB = ((long)b * M_PAD + (long)tj * TILE) * 8;
#pragma unroll
        for (int it = 0; it < 4; it++) {
            int idx = it * 256 + tid;        // 0..1023
            int row = idx >> 3, seg = idx & 7;
            int so = row * ROWB + seg * 16;
            long offA = baseA + row * 8 + seg;
            *reinterpret_cast<uint4*>(smem + A_HI + so) = hi4[offA];
            *reinterpret_cast<uint4*>(smem + A_LO + so) = lo4[offA];
            if (!diag) {
                long offB = baseB + row * 8 + seg;
                *reinterpret_cast<uint4*>(smem + B_HI + so) = hi4[offB];
                *reinterpret_cast<uint4*>(smem + B_LO + so) = lo4[offB];
            }
        }
    }
    __syncthreads();

    const uint32_t sb = smem_u32(smem);
    const uint32_t a_lane = (uint32_t)(wr * 64 + (lid & 15)) * ROWB + (lid >> 4) * 16;
    const uint32_t b_lane = (uint32_t)(wc * 32 + (lid & 15)) * ROWB + (lid >> 4) * 16;
    const uint32_t aoff_h = sb + A_HI + a_lane;
    const uint32_t aoff_l = sb + A_LO + a_lane;
    const uint32_t boff_h = sb + B_HI + b_lane;
    const uint32_t boff_l = sb + B_LO + b_lane;

    float acc[4][4][4];
#pragma unroll
    for (int mt = 0; mt < 4; mt++)
#pragma unroll
        for (int nt = 0; nt < 4; nt++)
#pragma unroll
            for (int q = 0; q < 4; q++) acc[mt][nt][q] = 0.0f;

    // Mainloop: acc += Ah*Bh + Ah*Bl + Al*Bh  (A fragments reused across 2 of 3)
#pragma unroll
    for (int k = 0; k < 4; k++) {
        uint32_t af[4][4], bh[2][4], bl[2][4];
#pragma unroll
        for (int mt = 0; mt < 4; mt++)
            ldsm_x4(af[mt], aoff_h + mt * 16 * ROWB + k * 32);
#pragma unroll
        for (int bt = 0; bt < 2; bt++) {
            ldsm_x4(bh[bt], boff_h + bt * 16 * ROWB + k * 32);
            ldsm_x4(bl[bt], boff_l + bt * 16 * ROWB + k * 32);
        }
#pragma unroll
        for (int mt = 0; mt < 4; mt++)
#pragma unroll
            for (int nt = 0; nt < 4; nt++) {
                mma16816(acc[mt][nt], af[mt],
                         bh[nt >> 1][nt & 1], bh[nt >> 1][(nt & 1) + 2]);
                mma16816(acc[mt][nt], af[mt],
                         bl[nt >> 1][nt & 1], bl[nt >> 1][(nt & 1) + 2]);
            }
#pragma unroll
        for (int mt = 0; mt < 4; mt++)
            ldsm_x4(af[mt], aoff_l + mt * 16 * ROWB + k * 32);   // reuse af
#pragma unroll
        for (int mt = 0; mt < 4; mt++)
#pragma unroll
            for (int nt = 0; nt < 4; nt++)
                mma16816(acc[mt][nt], af[mt],
                         bh[nt >> 1][nt & 1], bh[nt >> 1][(nt & 1) + 2]);
    }

    // Operand SMEM is dead after ALL warps pass this barrier.
    __syncthreads();

    // --- Epilogue ----------------------------------------------------------
    float* tile_s = reinterpret_cast<float*>(smem);   // [c][r], pitch TPITCH
    const int lrow0 = wr * 64 + (lid >> 2);
    const int lcol0 = wc * 32 + (lid & 3) * 2;
    const long M = M_OUT;

#pragma unroll
    for (int mt = 0; mt < 4; mt++) {
#pragma unroll
        for (int nt = 0; nt < 4; nt++) {
            int lc = lcol0 + nt * 8;
#pragma unroll
            for (int h = 0; h < 2; h++) {
                int lr = lrow0 + mt * 16 + h * 8;
                float2 v;
                v.x = tanh_relu(acc[mt][nt][h * 2 + 0]);
                v.y = tanh_relu(acc[mt][nt][h * 2 + 1]);
                if (diag) {                    // self loops live on diag tiles
                    if (lr == lc)     v.x += 0.5f;
                    if (lr == lc + 1) v.y += 0.5f;
                }
                int gr = ti * TILE + lr, gc = tj * TILE + lc;
                if (gr < M_OUT && gc < M_OUT)
                    *reinterpret_cast<float2*>(out + ((long)b * M + gr) * M + gc) = v;
                if (!diag) {                   // transposed copy for mirror tile
                    tile_s[(lc + 0) * TPITCH + lr] = v.x;   // conflict-free
                    tile_s[(lc + 1) * TPITCH + lr] = v.y;
                }
            }
        }
    }

    if (!diag) {
        __syncthreads();
        // Mirror tile at (tj, ti): rows tj*128+c, cols ti*128+r. Coalesced
        // float4 stores; smem reads conflict-free (32 lanes sweep one row).
#pragma unroll
        for (int it = 0; it < 16; it++) {
            int e  = it * 256 + tid;           // 0..4095 float4 slots
            int c  = e >> 5;                   // 0..127
            int rq = e & 31;                   // float4 index within row
            float4 w = *reinterpret_cast<float4*>(tile_s + c * TPITCH + rq * 4);
            int gr = tj * TILE + c;            // ti<tj<=16 -> cols always valid
            if (gr < M_OUT)
                *reinterpret_cast<float4*>(
                    out + ((long)b * M + gr) * M + ti * TILE + rq * 4) = w;
        }
    }
}

// ---------------------------------------------------------------------------
extern "C" void kernel_launch(void* const* d_in, const int* in_sizes, int n_in,
                              void* d_out, int out_size) {
    const float* sp = (const float*)d_in[0];
    const float* tp = (const float*)d_in[1];
    if (n_in >= 2 && in_sizes[0] < in_sizes[1]) {
        sp = (const float*)d_in[1];
        tp = (const float*)d_in[0];
    }
    float* out = (float*)d_out;

    const int TOT = B_ * M_PAD * (KD / 4);
    convert_split_kernel<<<(TOT + 255) / 256, 256>>>(
        (const float4*)sp, (const float4*)tp);

    cudaFuncSetAttribute(gram_kernel,
                         cudaFuncAttributeMaxDynamicSharedMemorySize, SMEM_BYTES);
    dim3 grid(NPAIRS, B_);
    gram_kernel<<<grid, 256, SMEM_BYTES>>>(out);
}